// round 7
// baseline (speedup 1.0000x reference)
#include <cuda_runtime.h>
#include <cuda_bf16.h>
#include <cstdint>

// out = sum_i | cumsum(x0 - x1)_i |, x = d_in[0] as (2, N) fp32, N = 2^23.
// Single-pass decoupled-lookback scan. 296 blocks (2/SM co-resident), 1024 thr,
// 112 KB dynamic smem each.
//   Per block: load chunk, diff -> smem, block aggregate; publish {gen,sum} (64-bit);
//   warp 0 spin-reads predecessors' aggregates -> exclusive block prefix (no global
//   barrier); tile scans from smem -> sum|cdf| partial; atomic done-counter; last
//   block reduces 296 partials in fp64, writes scalar, resets for next graph replay.

#define GRID_N   296
#define TPB      1024
#define NWARP    32
#define BLK_F4   7168             // float4 per block (28672 elems, 112 KB smem)
#define WARP_F4  224              // float4 per warp
#define LANE_J   7                // tiles per warp

typedef unsigned long long ull;

__device__ ull      g_pub[GRID_N];        // {tag:32 | fp32 aggregate:32}
__device__ float    g_partials[GRID_N];
__device__ unsigned g_done;               // zero-init
__device__ unsigned g_gen = 1;            // generation (stale tags = old gens)

__global__ void __launch_bounds__(TPB, 2) emd_scan(const float* __restrict__ x,
                                                   float* __restrict__ out, int N) {
    extern __shared__ float4 sdiff[];     // BLK_F4 float4
    __shared__ float    sWarpSums[NWARP];
    __shared__ float    sWarpAcc[NWARP];
    __shared__ float    sBlockPrefix;
    __shared__ unsigned sGen;
    __shared__ unsigned sLast;

    const int  tid  = threadIdx.x;
    const int  w    = tid >> 5;
    const int  lane = tid & 31;
    const int  bid  = blockIdx.x;
    const long tot4 = (long)N / 4;        // 2^21 float4

    if (tid == 0) sGen = *(volatile unsigned*)&g_gen;

    const float4* x0 = (const float4*)x;
    const float4* x1 = (const float4*)(x + N);

    const long blockStart4 = (long)bid * BLK_F4;
    const int  warpLocal4  = w * WARP_F4;

    // ---------------- Phase A: DRAM -> smem diffs + warp sums ----------------
    float s = 0.f;
#pragma unroll
    for (int j = 0; j < LANE_J; ++j) {
        long base = blockStart4 + warpLocal4 + j * 32;   // multiple of 32
        if (base < tot4) {
            long t4 = base + lane;
            float4 a = x0[t4];
            float4 b = x1[t4];
            float4 d;
            d.x = a.x - b.x; d.y = a.y - b.y; d.z = a.z - b.z; d.w = a.w - b.w;
            sdiff[warpLocal4 + j * 32 + lane] = d;
            s += (d.x + d.y) + (d.z + d.w);
        }
    }
#pragma unroll
    for (int off = 16; off; off >>= 1)
        s += __shfl_down_sync(0xffffffffu, s, off);
    if (lane == 0) sWarpSums[w] = s;
    __syncthreads();

    // ---------------- Publish aggregate + decoupled lookback (warp 0) ----------------
    if (w == 0) {
        const unsigned gen = sGen;
        // block aggregate from 32 warp sums
        float bs = sWarpSums[lane];
#pragma unroll
        for (int off = 16; off; off >>= 1)
            bs += __shfl_down_sync(0xffffffffu, bs, off);
        if (lane == 0)
            atomicExch(&g_pub[bid], ((ull)gen << 32) | (ull)__float_as_uint(bs));

        // exclusive prefix = sum of all predecessors' aggregates
        float p = 0.f;
        for (int j = lane; j < bid; j += 32) {
            ull pk;
            do { pk = *(volatile ull*)&g_pub[j]; }
            while ((unsigned)(pk >> 32) != gen);
            p += __uint_as_float((unsigned)pk);
        }
#pragma unroll
        for (int off = 16; off; off >>= 1)
            p += __shfl_down_sync(0xffffffffu, p, off);
        if (lane == 0) sBlockPrefix = p;
    }
    __syncthreads();

    // ---------------- Phase B: tile scans from smem, sum|cdf| ----------------
    float carry = sBlockPrefix;
    for (int i = 0; i < w; ++i) carry += sWarpSums[i];

    float acc = 0.f;
#pragma unroll
    for (int j = 0; j < LANE_J; ++j) {
        long base = blockStart4 + warpLocal4 + j * 32;
        if (base < tot4) {
            float4 d = sdiff[warpLocal4 + j * 32 + lane];  // conflict-free LDS.128
            float s0 = d.x;
            float s1 = s0 + d.y;
            float s2 = s1 + d.z;
            float s3 = s2 + d.w;

            float v = s3;                  // warp inclusive scan of lane totals
#pragma unroll
            for (int off = 1; off < 32; off <<= 1) {
                float n = __shfl_up_sync(0xffffffffu, v, off);
                if (lane >= off) v += n;
            }
            float bp = carry + (v - s3);   // lane-exclusive prefix
            acc += fabsf(bp + s0) + fabsf(bp + s1)
                 + fabsf(bp + s2) + fabsf(bp + s3);
            carry += __shfl_sync(0xffffffffu, v, 31);
        }
    }
#pragma unroll
    for (int off = 16; off; off >>= 1)
        acc += __shfl_down_sync(0xffffffffu, acc, off);
    if (lane == 0) sWarpAcc[w] = acc;
    __syncthreads();

    // ---------------- Completion: partial + done counter ----------------
    if (tid == 0) {
        float bp = 0.f;
#pragma unroll
        for (int i = 0; i < NWARP; ++i) bp += sWarpAcc[i];
        atomicExch(&g_partials[bid], bp);     // L2-coherent store
        __threadfence();
        unsigned old = atomicAdd(&g_done, 1u);
        sLast = (old == GRID_N - 1) ? 1u : 0u;
    }
    __syncthreads();

    // ---------------- Finisher: last block reduces + resets ----------------
    if (sLast && w == 0) {
        double p = 0.0;
        for (int i = lane; i < GRID_N; i += 32)
            p += (double)(*(volatile float*)&g_partials[i]);
#pragma unroll
        for (int off = 16; off; off >>= 1)
            p += __shfl_down_sync(0xffffffffu, p, off);
        if (lane == 0) {
            out[0] = (float)p;
            *(volatile unsigned*)&g_done = 0;     // reset for next replay
            __threadfence();
            *(volatile unsigned*)&g_gen = sGen + 1;  // invalidate g_pub tags
        }
    }
}

extern "C" void kernel_launch(void* const* d_in, const int* in_sizes, int n_in,
                              void* d_out, int out_size) {
    const float* x = (const float*)d_in[0];
    int N = in_sizes[0] / 2;                  // 8388608
    size_t smem = (size_t)BLK_F4 * sizeof(float4);   // 114688 B

    static bool attr_done = false;
    if (!attr_done) {
        cudaFuncSetAttribute(emd_scan,
                             cudaFuncAttributeMaxDynamicSharedMemorySize,
                             (int)smem);
        attr_done = true;
    }
    emd_scan<<<GRID_N, TPB, smem>>>(x, (float*)d_out, N);
}